// round 3
// baseline (speedup 1.0000x reference)
#include <cuda_runtime.h>
#include <math.h>

#define N_NODES   8192
#define K_NBR     64
#define TWO_N     (2 * N_NODES)
#define BN_EPS    1e-3f

// Split-K GEMV config
#define COL_TILES      8                       // 8192 / 1024 cols-per-block
#define ROW_CHUNKS     32                      // 16384 / 512 rows-per-chunk
#define ROWS_PER_CHUNK (TWO_N / ROW_CHUNKS)    // 512
#define THREADS_B      256                     // each thread owns 4 cols (float4)

// K1 config
#define K1_BLOCKS        64
#define K1_THREADS       256                   // 8 warps
#define NODES_PER_WARP   16                    // 64 blocks * 8 warps * 16 = 8192

// scratch (no allocation allowed in kernel_launch)
__device__ float g_h[TWO_N];
__device__ float g_part[ROW_CHUNKS * N_NODES];

// ---------------------------------------------------------------------------
// K1: gather neighbors (from SMEM-resident x), sum, BN,
//     build h = concat(BN(x), BN(x + ngh_sum)).
// x (32KB) is preloaded into shared memory; random gathers hit the smem
// crossbar (~conflict-degree cycles) instead of costing ~32 L1 wavefronts
// per warp-LDG. adj rows are read as int2 (one LDG.64 per node per warp).
// ---------------------------------------------------------------------------
__global__ __launch_bounds__(K1_THREADS)
void build_h_kernel(const float* __restrict__ x,
                    const int* __restrict__ adj,
                    const float* __restrict__ gamma,
                    const float* __restrict__ beta,
                    const float* __restrict__ mean,
                    const float* __restrict__ var)
{
    __shared__ float sx[N_NODES];   // 32 KB

    // cooperative preload of x: 8192 floats / 256 threads = 8 float4 each
    {
        const float4* x4 = reinterpret_cast<const float4*>(x);
        float4* s4 = reinterpret_cast<float4*>(sx);
        #pragma unroll
        for (int i = 0; i < 8; ++i)
            s4[threadIdx.x + i * K1_THREADS] = x4[threadIdx.x + i * K1_THREADS];
    }
    __syncthreads();

    const int warpId = threadIdx.x >> 5;
    const int lane   = threadIdx.x & 31;
    const int nodeBase = (blockIdx.x * (K1_THREADS >> 5) + warpId) * NODES_PER_WARP;

    #pragma unroll 2
    for (int it = 0; it < NODES_PER_WARP; ++it) {
        const int node = nodeBase + it;
        // one LDG.64 per lane covers the 64-neighbor row
        int2 a = *reinterpret_cast<const int2*>(adj + node * K_NBR + lane * 2);
        float s = sx[a.x] + sx[a.y];

        #pragma unroll
        for (int off = 16; off > 0; off >>= 1)
            s += __shfl_down_sync(0xffffffffu, s, off);

        if (lane == 0) {
            float xv = sx[node];
            {   // BN for h[node] (raw x part)
                float inv = rsqrtf(var[node] + BN_EPS);
                g_h[node] = (xv - mean[node]) * inv * gamma[node] + beta[node];
            }
            {   // BN for h[N + node] (agg part)
                int j = N_NODES + node;
                float agg = xv + s;
                float inv = rsqrtf(var[j] + BN_EPS);
                g_h[j] = (agg - mean[j]) * inv * gamma[j] + beta[j];
            }
        }
    }
}

// ---------------------------------------------------------------------------
// K2: split-K GEMV partials. grid = (COL_TILES, ROW_CHUNKS) = 256 blocks,
// all co-resident (no wave tail). Each block caches 512 h values in smem;
// each thread streams a float4 column slice of W with __ldcs (read-once,
// evict-first). Unroll 16 -> 16 outstanding 16B loads per thread.
// partial[chunk][col] written exactly once -> deterministic.
// ---------------------------------------------------------------------------
__global__ __launch_bounds__(THREADS_B)
void gemv_partial_kernel(const float* __restrict__ W)
{
    __shared__ float sh[ROWS_PER_CHUNK];

    const int colBase = blockIdx.x * (THREADS_B * 4) + threadIdx.x * 4;
    const int rowBase = blockIdx.y * ROWS_PER_CHUNK;

    // load h chunk into smem (512 floats / 256 threads)
    sh[threadIdx.x]             = g_h[rowBase + threadIdx.x];
    sh[threadIdx.x + THREADS_B] = g_h[rowBase + threadIdx.x + THREADS_B];
    __syncthreads();

    float4 acc = make_float4(0.f, 0.f, 0.f, 0.f);
    const float4* wp = reinterpret_cast<const float4*>(
        W + (long long)rowBase * N_NODES + colBase);
    const int strideV = N_NODES / 4;   // float4 stride per row

    #pragma unroll 16
    for (int r = 0; r < ROWS_PER_CHUNK; ++r) {
        float  hv = sh[r];
        float4 w  = __ldcs(wp);
        acc.x = fmaf(hv, w.x, acc.x);
        acc.y = fmaf(hv, w.y, acc.y);
        acc.z = fmaf(hv, w.z, acc.z);
        acc.w = fmaf(hv, w.w, acc.w);
        wp += strideV;
    }

    *reinterpret_cast<float4*>(&g_part[blockIdx.y * N_NODES + colBase]) = acc;
}

// ---------------------------------------------------------------------------
// K3: reduce partials, add bias, exact-erf gelu, write output.
// ---------------------------------------------------------------------------
__global__ void reduce_gelu_kernel(const float* __restrict__ bias,
                                   float* __restrict__ out)
{
    const int j = blockIdx.x * blockDim.x + threadIdx.x;
    if (j >= N_NODES) return;

    float s = 0.f;
    #pragma unroll
    for (int c = 0; c < ROW_CHUNKS; ++c)
        s += g_part[c * N_NODES + j];

    float z = s + bias[j];
    // exact gelu: 0.5 * z * (1 + erf(z / sqrt(2)))
    out[j] = 0.5f * z * (1.0f + erff(z * 0.70710678118654752440f));
}

// ---------------------------------------------------------------------------
extern "C" void kernel_launch(void* const* d_in, const int* in_sizes, int n_in,
                              void* d_out, int out_size)
{
    const float* x     = (const float*)d_in[0];  // input_data [1,N]
    const int*   adj   = (const int*)d_in[1];    // adj [N,K] int32 (JAX x64 off)
    // d_in[2] = edge_weights (unused by reference)
    const float* W     = (const float*)d_in[3];  // [2N, N]
    const float* b     = (const float*)d_in[4];  // [N]
    const float* gamma = (const float*)d_in[5];  // [2N]
    const float* beta  = (const float*)d_in[6];  // [2N]
    const float* mean  = (const float*)d_in[7];  // [2N]
    const float* var   = (const float*)d_in[8];  // [2N]
    float*       out   = (float*)d_out;

    build_h_kernel<<<K1_BLOCKS, K1_THREADS>>>(x, adj, gamma, beta, mean, var);

    dim3 grid2(COL_TILES, ROW_CHUNKS);
    gemv_partial_kernel<<<grid2, THREADS_B>>>(W);

    reduce_gelu_kernel<<<(N_NODES + 255) / 256, 256>>>(b, out);
}

// round 4
// speedup vs baseline: 1.1105x; 1.1105x over previous
#include <cuda_runtime.h>
#include <math.h>

#define N_NODES   8192
#define K_NBR     64
#define TWO_N     (2 * N_NODES)
#define BN_EPS    1e-3f

// Split-K GEMV config: grid (8, 74) = 592 blocks = 148 SMs * 4 exactly.
// Row ranges are integer-partitioned: group g owns [g*2N/74, (g+1)*2N/74).
#define COL_TILES   8
#define ROW_GROUPS  74
#define MAX_ROWS    224          // ceil(16384/74)=222, padded
#define THREADS_B   256          // each thread owns 4 cols (float4)

// K1 config: 256 blocks * 8 warps * 4 nodes = 8192
#define K1_BLOCKS   256
#define K1_THREADS  256
#define NODES_PER_WARP 4

// scratch (no allocation allowed in kernel_launch)
__device__ float g_h[TWO_N];
__device__ float g_part[ROW_GROUPS * N_NODES];

// ---------------------------------------------------------------------------
// K1: gather neighbors from SMEM-resident x, sum, BN,
//     h = concat(BN(x), BN(x + ngh_sum)).
// 256 blocks so every SM is busy (R3's 64-block version starved the chip).
// Each warp handles 4 nodes with interleaved reduction chains (ILP hides
// the ~26cyc shuffle latency). adj rows read as int2 (LDG.64).
// ---------------------------------------------------------------------------
__global__ __launch_bounds__(K1_THREADS)
void build_h_kernel(const float* __restrict__ x,
                    const int* __restrict__ adj,
                    const float* __restrict__ gamma,
                    const float* __restrict__ beta,
                    const float* __restrict__ mean,
                    const float* __restrict__ var)
{
    __shared__ float sx[N_NODES];   // 32 KB

    // cooperative preload of x: 8192 floats / 256 threads = 8 float4 each
    {
        const float4* x4 = reinterpret_cast<const float4*>(x);
        float4* s4 = reinterpret_cast<float4*>(sx);
        #pragma unroll
        for (int i = 0; i < 8; ++i)
            s4[threadIdx.x + i * K1_THREADS] = x4[threadIdx.x + i * K1_THREADS];
    }
    __syncthreads();

    const int warpId = threadIdx.x >> 5;
    const int lane   = threadIdx.x & 31;
    const int nodeBase = (blockIdx.x * (K1_THREADS >> 5) + warpId) * NODES_PER_WARP;

    // batch the adj loads (MLP), then gather, then interleaved reductions
    int2 a[NODES_PER_WARP];
    const int2* adj2 = reinterpret_cast<const int2*>(adj);
    #pragma unroll
    for (int i = 0; i < NODES_PER_WARP; ++i)
        a[i] = adj2[(nodeBase + i) * 32 + lane];

    float s[NODES_PER_WARP];
    #pragma unroll
    for (int i = 0; i < NODES_PER_WARP; ++i)
        s[i] = sx[a[i].x] + sx[a[i].y];

    #pragma unroll
    for (int off = 16; off > 0; off >>= 1) {
        #pragma unroll
        for (int i = 0; i < NODES_PER_WARP; ++i)
            s[i] += __shfl_down_sync(0xffffffffu, s[i], off);
    }

    if (lane == 0) {
        #pragma unroll
        for (int i = 0; i < NODES_PER_WARP; ++i) {
            const int node = nodeBase + i;
            float xv = sx[node];
            {   // BN for h[node] (raw x part)
                float inv = rsqrtf(var[node] + BN_EPS);
                g_h[node] = (xv - mean[node]) * inv * gamma[node] + beta[node];
            }
            {   // BN for h[N + node] (agg part)
                int j = N_NODES + node;
                float agg = xv + s[i];
                float inv = rsqrtf(var[j] + BN_EPS);
                g_h[j] = (agg - mean[j]) * inv * gamma[j] + beta[j];
            }
        }
    }
}

// ---------------------------------------------------------------------------
// K2: split-K GEMV partials, perfectly load-balanced.
// grid = (COL_TILES, ROW_GROUPS) = (8, 74) = 592 blocks = 4 per SM exactly;
// row group g owns rows [g*2N/74, (g+1)*2N/74) (221 or 222 rows, <0.5% skew).
// Each block caches its h rows in smem; each thread streams a float4 column
// slice of W (coalesced LDG.128). partial written once -> deterministic.
// ---------------------------------------------------------------------------
__global__ __launch_bounds__(THREADS_B)
void gemv_partial_kernel(const float* __restrict__ W)
{
    __shared__ float sh[MAX_ROWS];

    const int colBase  = blockIdx.x * (THREADS_B * 4) + threadIdx.x * 4;
    const int rowStart = (blockIdx.y * TWO_N) / ROW_GROUPS;
    const int rowEnd   = ((blockIdx.y + 1) * TWO_N) / ROW_GROUPS;
    const int nRows    = rowEnd - rowStart;

    if (threadIdx.x < nRows)  sh[threadIdx.x] = g_h[rowStart + threadIdx.x];
    {
        int i2 = threadIdx.x + THREADS_B;
        if (i2 < nRows) sh[i2] = g_h[rowStart + i2];
    }
    __syncthreads();

    float4 acc = make_float4(0.f, 0.f, 0.f, 0.f);
    const float4* wp = reinterpret_cast<const float4*>(
        W + (long long)rowStart * N_NODES + colBase);
    const int strideV = N_NODES / 4;

    #pragma unroll 8
    for (int r = 0; r < nRows; ++r) {
        float  hv = sh[r];
        float4 w  = wp[(long long)r * strideV];
        acc.x = fmaf(hv, w.x, acc.x);
        acc.y = fmaf(hv, w.y, acc.y);
        acc.z = fmaf(hv, w.z, acc.z);
        acc.w = fmaf(hv, w.w, acc.w);
    }

    *reinterpret_cast<float4*>(&g_part[blockIdx.y * N_NODES + colBase]) = acc;
}

// ---------------------------------------------------------------------------
// K3: reduce 74 partials, add bias, exact-erf gelu, write output.
// ---------------------------------------------------------------------------
__global__ void reduce_gelu_kernel(const float* __restrict__ bias,
                                   float* __restrict__ out)
{
    const int j = blockIdx.x * blockDim.x + threadIdx.x;
    if (j >= N_NODES) return;

    float s = 0.f;
    #pragma unroll
    for (int c = 0; c < ROW_GROUPS; ++c)
        s += g_part[c * N_NODES + j];

    float z = s + bias[j];
    out[j] = 0.5f * z * (1.0f + erff(z * 0.70710678118654752440f));
}

// ---------------------------------------------------------------------------
extern "C" void kernel_launch(void* const* d_in, const int* in_sizes, int n_in,
                              void* d_out, int out_size)
{
    const float* x     = (const float*)d_in[0];  // input_data [1,N]
    const int*   adj   = (const int*)d_in[1];    // adj [N,K] int32 (JAX x64 off)
    // d_in[2] = edge_weights (unused by reference)
    const float* W     = (const float*)d_in[3];  // [2N, N]
    const float* b     = (const float*)d_in[4];  // [N]
    const float* gamma = (const float*)d_in[5];  // [2N]
    const float* beta  = (const float*)d_in[6];  // [2N]
    const float* mean  = (const float*)d_in[7];  // [2N]
    const float* var   = (const float*)d_in[8];  // [2N]
    float*       out   = (float*)d_out;

    build_h_kernel<<<K1_BLOCKS, K1_THREADS>>>(x, adj, gamma, beta, mean, var);

    dim3 grid2(COL_TILES, ROW_GROUPS);
    gemv_partial_kernel<<<grid2, THREADS_B>>>(W);

    reduce_gelu_kernel<<<(N_NODES + 255) / 256, 256>>>(b, out);
}

// round 5
// speedup vs baseline: 1.1225x; 1.0108x over previous
#include <cuda_runtime.h>
#include <math.h>

#define N_NODES   8192
#define K_NBR     64
#define TWO_N     (2 * N_NODES)
#define BN_EPS    1e-3f

// Split-K GEMV config: grid (8, 128) = 1024 blocks (~6.9/SM), each chunk
// is a compile-time-constant 128 rows (full MLP batching in SASS).
#define COL_TILES      8
#define ROW_CHUNKS     128
#define ROWS_PER_CHUNK (TWO_N / ROW_CHUNKS)    // 128
#define THREADS_B      256                     // each thread owns 4 cols (float4)

// K1 config: 128 blocks x 1024 threads; 64 nodes/block, 2 nodes/warp
#define K1_BLOCKS   128
#define K1_THREADS  1024

// scratch (no allocation allowed in kernel_launch)
__device__ float g_h[TWO_N];
__device__ float g_part[ROW_CHUNKS * N_NODES];

// ---------------------------------------------------------------------------
// K1: gather neighbors from SMEM-resident x, sum, BN,
//     h = concat(BN(x), BN(x + ngh_sum)).
// Big blocks minimize the x-preload tax (128 x 32KB = 4MB L2 total);
// random gathers hit the smem crossbar (~5 cyc) instead of costing ~32 L1
// wavefronts per warp-LDG. Two interleaved nodes per warp hide shuffle lat.
// ---------------------------------------------------------------------------
__global__ __launch_bounds__(K1_THREADS)
void build_h_kernel(const float* __restrict__ x,
                    const int* __restrict__ adj,
                    const float* __restrict__ gamma,
                    const float* __restrict__ beta,
                    const float* __restrict__ mean,
                    const float* __restrict__ var)
{
    __shared__ float sx[N_NODES];   // 32 KB

    // cooperative preload: 2048 float4 / 1024 threads = 2 each
    {
        const float4* x4 = reinterpret_cast<const float4*>(x);
        float4* s4 = reinterpret_cast<float4*>(sx);
        s4[threadIdx.x]        = x4[threadIdx.x];
        s4[threadIdx.x + 1024] = x4[threadIdx.x + 1024];
    }
    __syncthreads();

    const int warpId = threadIdx.x >> 5;
    const int lane   = threadIdx.x & 31;
    const int nodeBase = blockIdx.x * 64 + warpId * 2;

    const int2* adj2 = reinterpret_cast<const int2*>(adj);
    int2 a0 = adj2[nodeBase * 32 + lane];
    int2 a1 = adj2[(nodeBase + 1) * 32 + lane];

    float s0 = sx[a0.x] + sx[a0.y];
    float s1 = sx[a1.x] + sx[a1.y];

    #pragma unroll
    for (int off = 16; off > 0; off >>= 1) {
        s0 += __shfl_down_sync(0xffffffffu, s0, off);
        s1 += __shfl_down_sync(0xffffffffu, s1, off);
    }

    if (lane == 0) {
        #pragma unroll
        for (int i = 0; i < 2; ++i) {
            const int node = nodeBase + i;
            const float ss = (i == 0) ? s0 : s1;
            float xv = sx[node];
            {   // BN for h[node] (raw x part)
                float inv = rsqrtf(var[node] + BN_EPS);
                g_h[node] = (xv - mean[node]) * inv * gamma[node] + beta[node];
            }
            {   // BN for h[N + node] (agg part)
                int j = N_NODES + node;
                float agg = xv + ss;
                float inv = rsqrtf(var[j] + BN_EPS);
                g_h[j] = (agg - mean[j]) * inv * gamma[j] + beta[j];
            }
        }
    }
}

// ---------------------------------------------------------------------------
// K2: split-K GEMV partials. grid (8,128) = 1024 blocks (~6.9/SM) gives
// ~100KB of W-bytes in flight per SM (vs the ~25KB BW*latency requirement),
// so HBM stays saturated. Compile-time 128-row trip count -> ptxas batches
// the LDG.128 front. Each partial written exactly once -> deterministic.
// ---------------------------------------------------------------------------
__global__ __launch_bounds__(THREADS_B)
void gemv_partial_kernel(const float* __restrict__ W)
{
    __shared__ float sh[ROWS_PER_CHUNK];

    const int colBase = blockIdx.x * (THREADS_B * 4) + threadIdx.x * 4;
    const int rowBase = blockIdx.y * ROWS_PER_CHUNK;

    if (threadIdx.x < ROWS_PER_CHUNK)
        sh[threadIdx.x] = g_h[rowBase + threadIdx.x];
    __syncthreads();

    float4 acc = make_float4(0.f, 0.f, 0.f, 0.f);
    const float4* wp = reinterpret_cast<const float4*>(
        W + (long long)rowBase * N_NODES + colBase);
    const int strideV = N_NODES / 4;

    #pragma unroll 16
    for (int r = 0; r < ROWS_PER_CHUNK; ++r) {
        float  hv = sh[r];
        float4 w  = wp[r * strideV];
        acc.x = fmaf(hv, w.x, acc.x);
        acc.y = fmaf(hv, w.y, acc.y);
        acc.z = fmaf(hv, w.z, acc.z);
        acc.w = fmaf(hv, w.w, acc.w);
    }

    *reinterpret_cast<float4*>(&g_part[blockIdx.y * N_NODES + colBase]) = acc;
}

// ---------------------------------------------------------------------------
// K3: reduce 128 partials (L2-resident, 4MB), add bias, exact-erf gelu.
// ---------------------------------------------------------------------------
__global__ void reduce_gelu_kernel(const float* __restrict__ bias,
                                   float* __restrict__ out)
{
    const int j = blockIdx.x * blockDim.x + threadIdx.x;
    if (j >= N_NODES) return;

    float s = 0.f;
    #pragma unroll 16
    for (int c = 0; c < ROW_CHUNKS; ++c)
        s += g_part[c * N_NODES + j];

    float z = s + bias[j];
    out[j] = 0.5f * z * (1.0f + erff(z * 0.70710678118654752440f));
}

// ---------------------------------------------------------------------------
extern "C" void kernel_launch(void* const* d_in, const int* in_sizes, int n_in,
                              void* d_out, int out_size)
{
    const float* x     = (const float*)d_in[0];  // input_data [1,N]
    const int*   adj   = (const int*)d_in[1];    // adj [N,K] int32 (JAX x64 off)
    // d_in[2] = edge_weights (unused by reference)
    const float* W     = (const float*)d_in[3];  // [2N, N]
    const float* b     = (const float*)d_in[4];  // [N]
    const float* gamma = (const float*)d_in[5];  // [2N]
    const float* beta  = (const float*)d_in[6];  // [2N]
    const float* mean  = (const float*)d_in[7];  // [2N]
    const float* var   = (const float*)d_in[8];  // [2N]
    float*       out   = (float*)d_out;

    build_h_kernel<<<K1_BLOCKS, K1_THREADS>>>(x, adj, gamma, beta, mean, var);

    dim3 grid2(COL_TILES, ROW_CHUNKS);
    gemv_partial_kernel<<<grid2, THREADS_B>>>(W);

    reduce_gelu_kernel<<<(N_NODES + 255) / 256, 256>>>(b, out);
}